// round 9
// baseline (speedup 1.0000x reference)
#include <cuda_runtime.h>
#include <cuda_bf16.h>
#include <math.h>
#include <stdint.h>

// Problem constants
#define B_  4
#define L_  2048
#define D_  1024
#define H_  16
#define DK_ 64
#define M_  (B_ * L_)      // 8192
#define N_  (H_ * DK_)     // 1024

// Scratch (device globals — no runtime allocation allowed)
__device__ float g_q[B_ * H_ * L_ * DK_];    // [B,H,L,DK] (tf32-rounded)
__device__ float g_k[B_ * H_ * L_ * DK_];
__device__ float g_v[B_ * H_ * L_ * DK_];
__device__ float g_ctx[B_ * L_ * H_ * DK_];  // [B,L,H*DV] (tf32-rounded)
__device__ uint32_t g_wt[4ull * D_ * N_];    // tf32-rounded weights, [k][n]
__device__ uint32_t g_qin[(size_t)M_ * D_];  // tf32-rounded inputs
__device__ uint32_t g_kin[(size_t)M_ * D_];
__device__ uint32_t g_vin[(size_t)M_ * D_];

// ---------------------------------------------------------------------------
// helpers
// ---------------------------------------------------------------------------
__device__ __forceinline__ uint32_t smem_u32(const void* p) {
    uint32_t a;
    asm("{ .reg .u64 t; cvta.to.shared.u64 t, %1; cvt.u32.u64 %0, t; }"
        : "=r"(a) : "l"(p));
    return a;
}
__device__ __forceinline__ uint32_t f2tf32(float v) {
    uint32_t r;
    asm("cvt.rna.tf32.f32 %0, %1;" : "=r"(r) : "f"(v));
    return r;
}
__device__ __forceinline__ float ex2(float x) {
    float r;
    asm("ex2.approx.ftz.f32 %0, %1;" : "=f"(r) : "f"(x));
    return r;
}
__device__ __forceinline__ void mma_tf32(float* c, const uint32_t* a,
                                         const uint32_t* b) {
    asm volatile(
        "mma.sync.aligned.m16n8k8.row.col.f32.tf32.tf32.f32 "
        "{%0,%1,%2,%3},{%4,%5,%6,%7},{%8,%9},{%0,%1,%2,%3};"
        : "+f"(c[0]), "+f"(c[1]), "+f"(c[2]), "+f"(c[3])
        : "r"(a[0]), "r"(a[1]), "r"(a[2]), "r"(a[3]), "r"(b[0]), "r"(b[1]));
}
#define CP_ASYNC16(dst, src)                                        \
    asm volatile("cp.async.cg.shared.global [%0], [%1], 16;" ::    \
                     "r"(dst), "l"(src))
#define CP_COMMIT() asm volatile("cp.async.commit_group;")
#define CP_WAIT0() asm volatile("cp.async.wait_group 0;")
#define CP_WAIT2() asm volatile("cp.async.wait_group 2;")

// ---------------------------------------------------------------------------
// Fused prepass: tf32-round query/key/value inputs + 4 weight matrices.
// Block = 1024 floats. Segments: 3x8192 blocks (inputs), 4x1024 (weights).
// ---------------------------------------------------------------------------
__global__ __launch_bounds__(256) void cvt_all(
    const float* __restrict__ q, const float* __restrict__ k,
    const float* __restrict__ v, const float* __restrict__ Wq,
    const float* __restrict__ Wk, const float* __restrict__ Wv,
    const float* __restrict__ Wo, uint32_t* __restrict__ qr,
    uint32_t* __restrict__ kr, uint32_t* __restrict__ vr,
    uint32_t* __restrict__ wt) {
    const int blk = blockIdx.x;
    const float* src;
    uint32_t* dst;
    int base;
    if (blk < 8192) { src = q; dst = qr; base = blk; }
    else if (blk < 16384) { src = k; dst = kr; base = blk - 8192; }
    else if (blk < 24576) { src = v; dst = vr; base = blk - 16384; }
    else {
        const int wseg = (blk - 24576) >> 10;
        base = (blk - 24576) & 1023;
        src = wseg == 0 ? Wq : wseg == 1 ? Wk : wseg == 2 ? Wv : Wo;
        dst = wt + (size_t)wseg * D_ * N_;
    }
    const size_t i = (size_t)base * 1024 + threadIdx.x * 4;
    float4 val = *(const float4*)&src[i];
    uint4 o;
    o.x = f2tf32(val.x); o.y = f2tf32(val.y);
    o.z = f2tf32(val.z); o.w = f2tf32(val.w);
    *(uint4*)&dst[i] = o;
}

// ---------------------------------------------------------------------------
// tf32 register-MMA GEMM, pure cp.async operands, 4-stage pipeline,
// one __syncthreads per iteration. Block 128x256, warp tile 64x64, BK=32.
// QKV fused via gridDim.z (A/bias/C selected per z).
// ---------------------------------------------------------------------------
#define AST 36     // A row stride words (32 + 4 pad)
#define BST 264    // B row stride words (256 + 8 pad)
#define ASW (128 * AST)                 // 4608 words
#define STGW (ASW + 32 * BST)           // 13056 words/stage
#define NSTG 4
#define GEMM_SMEM (NSTG * STGW * 4)     // 208896 B

template <bool SPLIT>
__global__ __launch_bounds__(256, 1) void gemm_cp(
    const uint32_t* __restrict__ A0, const uint32_t* __restrict__ A1,
    const uint32_t* __restrict__ A2, const uint32_t* __restrict__ Wt,
    const float* __restrict__ bias0, const float* __restrict__ bias1,
    const float* __restrict__ bias2, float* __restrict__ C0,
    float* __restrict__ C1, float* __restrict__ C2) {
    extern __shared__ uint32_t sh[];
    const uint32_t sbase = smem_u32(sh);
    const int z = blockIdx.z;
    const uint32_t* A = z == 0 ? A0 : z == 1 ? A1 : A2;
    const uint32_t* W = Wt + (size_t)z * D_ * N_;
    const float* bias = z == 0 ? bias0 : z == 1 ? bias1 : bias2;
    float* C = z == 0 ? C0 : z == 1 ? C1 : C2;

    const int tid = threadIdx.x;
    const int lane = tid & 31;
    const int warp = tid >> 5;
    const int wm = (warp >> 2) * 64;
    const int wn = (warp & 3) * 64;
    const int row0 = blockIdx.y * 128;
    const int col0 = blockIdx.x * 256;
    const int lr = lane >> 2;
    const int lc = lane & 3;

    float acc[4][8][4];
#pragma unroll
    for (int i = 0; i < 4; i++)
#pragma unroll
        for (int j = 0; j < 8; j++)
#pragma unroll
            for (int e = 0; e < 4; e++) acc[i][j][e] = 0.0f;

    auto cpAB = [&](int kt, int s) {
        // A: 128 rows x 32 k = 1024 16B chunks
#pragma unroll
        for (int it = 0; it < 4; it++) {
            const int cid = it * 256 + tid;
            const int r = cid >> 3;
            const int k4 = (cid & 7) * 4;
            const uint32_t dst = sbase + (s * STGW + r * AST + k4) * 4;
            CP_ASYNC16(dst, &A[(size_t)(row0 + r) * D_ + kt * 32 + k4]);
        }
        // B: 32 rows x 256 cols = 2048 16B chunks
#pragma unroll
        for (int it = 0; it < 8; it++) {
            const int cid = it * 256 + tid;
            const int r = cid >> 6;
            const int c4 = (cid & 63) * 4;
            const uint32_t dst = sbase + (s * STGW + ASW + r * BST + c4) * 4;
            CP_ASYNC16(dst, &W[(size_t)(kt * 32 + r) * N_ + col0 + c4]);
        }
        CP_COMMIT();
    };

    // prologue: stages 0..2 in flight
    cpAB(0, 0);
    cpAB(1, 1);
    cpAB(2, 2);

    for (int kt = 0; kt < 32; kt++) {
        const int s = kt & 3;
        CP_WAIT2();        // group kt complete
        __syncthreads();   // visible to all; stage (kt-1)&3 free for reuse
        if (kt < 29) cpAB(kt + 3, (kt + 3) & 3);
        else CP_COMMIT();  // keep group arithmetic exact

        const uint32_t* Ab = &sh[s * STGW];
        const uint32_t* Bb = &sh[s * STGW + ASW];
#pragma unroll
        for (int ks = 0; ks < 4; ks++) {
            const int k = ks * 8;
            uint32_t af[4][4];
#pragma unroll
            for (int mt = 0; mt < 4; mt++) {
                const int r = wm + mt * 16 + lr;
                af[mt][0] = Ab[r * AST + k + lc];
                af[mt][1] = Ab[(r + 8) * AST + k + lc];
                af[mt][2] = Ab[r * AST + k + 4 + lc];
                af[mt][3] = Ab[(r + 8) * AST + k + 4 + lc];
            }
#pragma unroll
            for (int nt = 0; nt < 8; nt++) {
                uint32_t bf[2];
                const int c = wn + nt * 8 + lr;
                bf[0] = Bb[(k + lc) * BST + c];
                bf[1] = Bb[(k + 4 + lc) * BST + c];
#pragma unroll
                for (int mt = 0; mt < 4; mt++) mma_tf32(acc[mt][nt], af[mt], bf);
            }
        }
    }

    // epilogue
#pragma unroll
    for (int mt = 0; mt < 4; mt++) {
#pragma unroll
        for (int nt = 0; nt < 8; nt++) {
            const int c = col0 + wn + nt * 8 + 2 * lc;
            const float bz0 = bias[c], bz1 = bias[c + 1];
#pragma unroll
            for (int half = 0; half < 2; half++) {
                const int m = row0 + wm + mt * 16 + lr + half * 8;
                float v0 = acc[mt][nt][half * 2 + 0] + bz0;
                float v1 = acc[mt][nt][half * 2 + 1] + bz1;
                if (SPLIT) {
                    v0 = __uint_as_float(f2tf32(v0));
                    v1 = __uint_as_float(f2tf32(v1));
                    const int b = m >> 11, l = m & (L_ - 1);
                    const int h = c >> 6, dk = c & (DK_ - 1);
                    float* p = &C[((((size_t)b * H_ + h) * L_) + l) * DK_ + dk];
                    p[0] = v0; p[1] = v1;
                } else {
                    C[(size_t)m * N_ + c] = v0;
                    C[(size_t)m * N_ + c + 1] = v1;
                }
            }
        }
    }
}

// ---------------------------------------------------------------------------
// Flash attention (round-8 version; ctx writes tf32-rounded for the O-proj).
// ---------------------------------------------------------------------------
#define KSTR 68
#define VSTR 72
#define PSTR 68
#define KOFF(s) ((s) * (64 * KSTR))
#define VOFF(s) (2 * 64 * KSTR + (s) * (64 * VSTR))
#define POFF (2 * 64 * KSTR + 2 * 64 * VSTR)
#define ATTN_SMEM ((POFF + 128 * PSTR) * 4)    // 106496

#define QSCALE 0.18033688011112042f  // 0.125 * log2(e)

__global__ __launch_bounds__(256, 2) void attn2(
    const float* __restrict__ q, const float* __restrict__ k,
    const float* __restrict__ v, float* __restrict__ ctx) {
    extern __shared__ uint32_t sh[];
    const uint32_t sbase = smem_u32(sh);
    const int tid = threadIdx.x;
    const int lane = tid & 31;
    const int warp = tid >> 5;
    const int lr = lane >> 2;
    const int lc = lane & 3;
    const int m0 = warp * 16;
    const int bh = blockIdx.y;
    const int q0 = blockIdx.x * 128;

    const float* qbase = q + (size_t)bh * L_ * DK_ + (size_t)q0 * DK_;
    const float* kbase = k + (size_t)bh * L_ * DK_;
    const float* vbase = v + (size_t)bh * L_ * DK_;

    auto cpKV = [&](int jn, int s) {
#pragma unroll
        for (int it = 0; it < 4; it++) {
            const int cid = it * 256 + tid;
            const int row = cid >> 4;
            const int c4 = (cid & 15) * 4;
            const uint32_t dk = sbase + (KOFF(s) + row * KSTR + c4) * 4;
            CP_ASYNC16(dk, &kbase[(size_t)(jn * 64 + row) * DK_ + c4]);
            const uint32_t dv = sbase + (VOFF(s) + row * VSTR + c4) * 4;
            CP_ASYNC16(dv, &vbase[(size_t)(jn * 64 + row) * DK_ + c4]);
        }
        CP_COMMIT();
    };

    // stage Q into P region + first KV tile
#pragma unroll
    for (int it = 0; it < 8; it++) {
        const int cid = it * 256 + tid;
        const int row = cid >> 4;
        const int c4 = (cid & 15) * 4;
        const uint32_t dst = sbase + (POFF + row * PSTR + c4) * 4;
        CP_ASYNC16(dst, &qbase[(size_t)row * DK_ + c4]);
    }
    CP_COMMIT();
    cpKV(0, 0);
    CP_WAIT0();
    __syncthreads();

    // Q fragments -> registers, scaled into ex2 domain
    uint32_t qf[8][4];
#pragma unroll
    for (int kt = 0; kt < 8; kt++) {
        const int kk = kt * 8;
        const uint32_t* P = &sh[POFF];
        uint32_t t0 = P[(m0 + lr) * PSTR + kk + lc];
        uint32_t t1 = P[(m0 + lr + 8) * PSTR + kk + lc];
        uint32_t t2 = P[(m0 + lr) * PSTR + kk + 4 + lc];
        uint32_t t3 = P[(m0 + lr + 8) * PSTR + kk + 4 + lc];
        qf[kt][0] = __float_as_uint(__uint_as_float(t0) * QSCALE);
        qf[kt][1] = __float_as_uint(__uint_as_float(t1) * QSCALE);
        qf[kt][2] = __float_as_uint(__uint_as_float(t2) * QSCALE);
        qf[kt][3] = __float_as_uint(__uint_as_float(t3) * QSCALE);
    }

    float oacc[8][4];
#pragma unroll
    for (int vt = 0; vt < 8; vt++)
#pragma unroll
        for (int e = 0; e < 4; e++) oacc[vt][e] = 0.0f;
    float mrow0 = -1e30f, mrow1 = -1e30f, lrow0 = 0.0f, lrow1 = 0.0f;

    for (int jt = 0; jt < 32; jt++) {
        const int s = jt & 1;
        if (jt > 0) {
            CP_WAIT0();
            __syncthreads();
        }
        if (jt < 31) cpKV(jt + 1, s ^ 1);

        const uint32_t* Kb = &sh[KOFF(s)];
        const uint32_t* Vb = &sh[VOFF(s)];
        uint32_t* Pb = &sh[POFF];

        // S = Q K^T  (log2-domain logits)
        float sacc[8][4];
#pragma unroll
        for (int nt = 0; nt < 8; nt++)
#pragma unroll
            for (int e = 0; e < 4; e++) sacc[nt][e] = 0.0f;
#pragma unroll
        for (int kt = 0; kt < 8; kt++) {
            const int kk = kt * 8;
#pragma unroll
            for (int nt = 0; nt < 8; nt++) {
                uint32_t bf[2];
                bf[0] = Kb[(nt * 8 + lr) * KSTR + kk + lc];
                bf[1] = Kb[(nt * 8 + lr) * KSTR + kk + 4 + lc];
                mma_tf32(sacc[nt], qf[kt], bf);
            }
        }

        // online softmax (ex2 domain)
        float mx0 = -1e30f, mx1 = -1e30f;
#pragma unroll
        for (int nt = 0; nt < 8; nt++) {
            mx0 = fmaxf(mx0, fmaxf(sacc[nt][0], sacc[nt][1]));
            mx1 = fmaxf(mx1, fmaxf(sacc[nt][2], sacc[nt][3]));
        }
        mx0 = fmaxf(mx0, __shfl_xor_sync(0xffffffffu, mx0, 1));
        mx0 = fmaxf(mx0, __shfl_xor_sync(0xffffffffu, mx0, 2));
        mx1 = fmaxf(mx1, __shfl_xor_sync(0xffffffffu, mx1, 1));
        mx1 = fmaxf(mx1, __shfl_xor_sync(0xffffffffu, mx1, 2));
        const float mn0 = fmaxf(mrow0, mx0);
        const float mn1 = fmaxf(mrow1, mx1);
        const float al0 = ex2(mrow0 - mn0);
        const float al1 = ex2(mrow1 - mn1);
        mrow0 = mn0; mrow1 = mn1;

        float sum0 = 0.0f, sum1 = 0.0f;
#pragma unroll
        for (int nt = 0; nt < 8; nt++) {
            const float p0 = ex2(sacc[nt][0] - mn0);
            const float p1 = ex2(sacc[nt][1] - mn0);
            const float p2 = ex2(sacc[nt][2] - mn1);
            const float p3 = ex2(sacc[nt][3] - mn1);
            sum0 += p0 + p1; sum1 += p2 + p3;
            const int c = nt * 8 + 2 * lc;
            uint32_t* pl = &Pb[(m0 + lr) * PSTR + c];
            pl[0] = f2tf32(p0); pl[1] = f2tf32(p1);
            uint32_t* ph = &Pb[(m0 + lr + 8) * PSTR + c];
            ph[0] = f2tf32(p2); ph[1] = f2tf32(p3);
        }
        sum0 += __shfl_xor_sync(0xffffffffu, sum0, 1);
        sum0 += __shfl_xor_sync(0xffffffffu, sum0, 2);
        sum1 += __shfl_xor_sync(0xffffffffu, sum1, 1);
        sum1 += __shfl_xor_sync(0xffffffffu, sum1, 2);
        lrow0 = lrow0 * al0 + sum0;
        lrow1 = lrow1 * al1 + sum1;
#pragma unroll
        for (int vt = 0; vt < 8; vt++) {
            oacc[vt][0] *= al0; oacc[vt][1] *= al0;
            oacc[vt][2] *= al1; oacc[vt][3] *= al1;
        }
        __syncwarp();

        // O += P V
#pragma unroll
        for (int pt = 0; pt < 8; pt++) {
            const int pp = pt * 8;
            uint32_t af[4];
            af[0] = Pb[(m0 + lr) * PSTR + pp + lc];
            af[1] = Pb[(m0 + lr + 8) * PSTR + pp + lc];
            af[2] = Pb[(m0 + lr) * PSTR + pp + 4 + lc];
            af[3] = Pb[(m0 + lr + 8) * PSTR + pp + 4 + lc];
#pragma unroll
            for (int vt = 0; vt < 8; vt++) {
                uint32_t bf[2];
                bf[0] = Vb[(pp + lc) * VSTR + vt * 8 + lr];
                bf[1] = Vb[(pp + 4 + lc) * VSTR + vt * 8 + lr];
                mma_tf32(oacc[vt], af, bf);
            }
        }
    }

    // epilogue: normalize, tf32-round, write ctx [B, L, H*DV]
    const int b = bh >> 4;
    const int h = bh & (H_ - 1);
    const float inv0 = 1.0f / lrow0;
    const float inv1 = 1.0f / lrow1;
    const int r0 = q0 + m0 + lr;
#pragma unroll
    for (int vt = 0; vt < 8; vt++) {
        const int c = h * DK_ + vt * 8 + 2 * lc;
        uint32_t* p0 = (uint32_t*)&ctx[((size_t)b * L_ + r0) * N_ + c];
        p0[0] = f2tf32(oacc[vt][0] * inv0);
        p0[1] = f2tf32(oacc[vt][1] * inv0);
        uint32_t* p1 = (uint32_t*)&ctx[((size_t)b * L_ + r0 + 8) * N_ + c];
        p1[0] = f2tf32(oacc[vt][2] * inv1);
        p1[1] = f2tf32(oacc[vt][3] * inv1);
    }
}

// ---------------------------------------------------------------------------
extern "C" void kernel_launch(void* const* d_in, const int* in_sizes, int n_in,
                              void* d_out, int out_size) {
    const float* query = (const float*)d_in[0];
    const float* key   = (const float*)d_in[1];
    const float* value = (const float*)d_in[2];
    const float* W_q   = (const float*)d_in[3];
    const float* b_q   = (const float*)d_in[4];
    const float* W_k   = (const float*)d_in[5];
    const float* b_k   = (const float*)d_in[6];
    const float* W_v   = (const float*)d_in[7];
    const float* b_v   = (const float*)d_in[8];
    const float* W_o   = (const float*)d_in[9];
    const float* b_o   = (const float*)d_in[10];
    float* out = (float*)d_out;

    float *qp, *kp, *vp, *cp;
    uint32_t *wt, *qin, *kin, *vin;
    cudaGetSymbolAddress((void**)&qp, g_q);
    cudaGetSymbolAddress((void**)&kp, g_k);
    cudaGetSymbolAddress((void**)&vp, g_v);
    cudaGetSymbolAddress((void**)&cp, g_ctx);
    cudaGetSymbolAddress((void**)&wt, g_wt);
    cudaGetSymbolAddress((void**)&qin, g_qin);
    cudaGetSymbolAddress((void**)&kin, g_kin);
    cudaGetSymbolAddress((void**)&vin, g_vin);

    cudaFuncSetAttribute(gemm_cp<true>,
                         cudaFuncAttributeMaxDynamicSharedMemorySize, GEMM_SMEM);
    cudaFuncSetAttribute(gemm_cp<false>,
                         cudaFuncAttributeMaxDynamicSharedMemorySize, GEMM_SMEM);
    cudaFuncSetAttribute(attn2, cudaFuncAttributeMaxDynamicSharedMemorySize,
                         ATTN_SMEM);

    // fused tf32 rounding prepass (inputs + weights)
    cvt_all<<<28672, 256>>>(query, key, value, W_q, W_k, W_v, W_o,
                            qin, kin, vin, wt);

    // fused QKV projections (grid.z selects input/bias/output)
    dim3 ggrid(N_ / 256, M_ / 128, 3);  // (4, 64, 3)
    gemm_cp<true><<<ggrid, 256, GEMM_SMEM>>>(qin, kin, vin, wt,
                                             b_q, b_k, b_v, qp, kp, vp);

    dim3 agrid(L_ / 128, B_ * H_);      // (16, 64)
    attn2<<<agrid, 256, ATTN_SMEM>>>(qp, kp, vp, cp);

    // output projection (ctx already tf32-rounded by attention epilogue)
    dim3 ogrid(N_ / 256, M_ / 128, 1);
    gemm_cp<false><<<ogrid, 256, GEMM_SMEM>>>(
        (const uint32_t*)cp, (const uint32_t*)cp, (const uint32_t*)cp,
        wt + 3ull * D_ * N_, b_o, b_o, b_o, out, out, out);
}

// round 15
// speedup vs baseline: 1.8197x; 1.8197x over previous
#include <cuda_runtime.h>
#include <cuda_fp16.h>
#include <math.h>
#include <stdint.h>

// Problem constants
#define B_  4
#define L_  2048
#define D_  1024
#define H_  16
#define DK_ 64
#define M_  (B_ * L_)      // 8192
#define N_  (H_ * DK_)     // 1024

#define QSCALE 0.18033688011112042f  // 0.125 * log2(e)

// Scratch (device globals — no runtime allocation allowed). 16B+ alignment
// required for cp.async/uint4 access paths.
__device__ __align__(256) __half g_q[(size_t)B_ * H_ * L_ * DK_];
__device__ __align__(256) __half g_k[(size_t)B_ * H_ * L_ * DK_];
__device__ __align__(256) __half g_v[(size_t)B_ * H_ * L_ * DK_];
__device__ __align__(256) __half g_ctx[(size_t)M_ * N_];
__device__ __align__(256) __half g_wth[4ull * D_ * N_];   // W^T: [n][k]
__device__ __align__(256) __half g_qin[(size_t)M_ * D_];
__device__ __align__(256) __half g_kin[(size_t)M_ * D_];
__device__ __align__(256) __half g_vin[(size_t)M_ * D_];

// ---------------------------------------------------------------------------
// helpers
// ---------------------------------------------------------------------------
__device__ __forceinline__ uint32_t smem_u32(const void* p) {
    uint32_t a;
    asm("{ .reg .u64 t; cvta.to.shared.u64 t, %1; cvt.u32.u64 %0, t; }"
        : "=r"(a) : "l"(p));
    return a;
}
__device__ __forceinline__ float ex2(float x) {
    float r;
    asm("ex2.approx.ftz.f32 %0, %1;" : "=f"(r) : "f"(x));
    return r;
}
// pack {hi, lo} floats -> one f16x2 register (lo = lower half)
__device__ __forceinline__ uint32_t h2pack(float hi, float lo) {
    uint32_t d;
    asm("cvt.rn.f16x2.f32 %0, %1, %2;" : "=r"(d) : "f"(hi), "f"(lo));
    return d;
}
__device__ __forceinline__ void mma_f16(float* c, const uint32_t* a,
                                        uint32_t b0, uint32_t b1) {
    asm volatile(
        "mma.sync.aligned.m16n8k16.row.col.f32.f16.f16.f32 "
        "{%0,%1,%2,%3},{%4,%5,%6,%7},{%8,%9},{%0,%1,%2,%3};"
        : "+f"(c[0]), "+f"(c[1]), "+f"(c[2]), "+f"(c[3])
        : "r"(a[0]), "r"(a[1]), "r"(a[2]), "r"(a[3]), "r"(b0), "r"(b1));
}
#define LDSM_X4(r0, r1, r2, r3, addr)                                   \
    asm volatile(                                                       \
        "ldmatrix.sync.aligned.m8n8.x4.shared.b16 {%0,%1,%2,%3}, [%4];" \
        : "=r"(r0), "=r"(r1), "=r"(r2), "=r"(r3) : "r"(addr))
#define LDSM_X4T(r0, r1, r2, r3, addr)                                        \
    asm volatile(                                                             \
        "ldmatrix.sync.aligned.m8n8.x4.trans.shared.b16 {%0,%1,%2,%3}, [%4];" \
        : "=r"(r0), "=r"(r1), "=r"(r2), "=r"(r3) : "r"(addr))
#define CP_ASYNC16(dst, src)                                     \
    asm volatile("cp.async.cg.shared.global [%0], [%1], 16;" :: \
                     "r"(dst), "l"(src))
#define CP_COMMIT() asm volatile("cp.async.commit_group;")
#define CP_WAIT0() asm volatile("cp.async.wait_group 0;")
#define CP_WAIT2() asm volatile("cp.async.wait_group 2;")

// ---------------------------------------------------------------------------
// Prepass 1: inputs fp32 -> fp16. 3 segments x 4096 blocks x 2048 elems.
// ---------------------------------------------------------------------------
__global__ __launch_bounds__(256) void cvt_in(
    const float* __restrict__ q, const float* __restrict__ k,
    const float* __restrict__ v, __half* __restrict__ qo,
    __half* __restrict__ ko, __half* __restrict__ vo) {
    const int blk = blockIdx.x;
    const int seg = blk >> 12;
    const int base = blk & 4095;
    const float* src = seg == 0 ? q : seg == 1 ? k : v;
    __half* dst = seg == 0 ? qo : seg == 1 ? ko : vo;
    const size_t i = (size_t)base * 2048 + threadIdx.x * 8;
    float4 a = *(const float4*)&src[i];
    float4 b = *(const float4*)&src[i + 4];
    uint4 o;
    o.x = h2pack(a.y, a.x); o.y = h2pack(a.w, a.z);
    o.z = h2pack(b.y, b.x); o.w = h2pack(b.w, b.z);
    *(uint4*)&dst[i] = o;
}

// ---------------------------------------------------------------------------
// Prepass 2: weights fp32 [k][n] -> fp16 transposed [n][k] (4 weights via z)
// ---------------------------------------------------------------------------
__global__ __launch_bounds__(256) void transp_w(
    const float* __restrict__ Wq, const float* __restrict__ Wk,
    const float* __restrict__ Wv, const float* __restrict__ Wo,
    __half* __restrict__ wt) {
    __shared__ float t[32][33];
    const int z = blockIdx.z;
    const float* W = z == 0 ? Wq : z == 1 ? Wk : z == 2 ? Wv : Wo;
    __half* Wt = wt + (size_t)z * D_ * N_;
    const int bx = blockIdx.x * 32, by = blockIdx.y * 32;
    const int x = threadIdx.x, y = threadIdx.y;  // 32 x 8
#pragma unroll
    for (int i = 0; i < 32; i += 8)
        t[y + i][x] = W[(size_t)(by + y + i) * N_ + bx + x];
    __syncthreads();
#pragma unroll
    for (int i = 0; i < 32; i += 8)
        Wt[(size_t)(bx + y + i) * D_ + by + x] = __float2half_rn(t[x][y + i]);
}

// ---------------------------------------------------------------------------
// fp16 GEMM: block 128x256, warp tile 64x64, BK=32 halfs, 4-stage cp.async,
// ldmatrix fragments. QKV fused via gridDim.z. C = A @ W + bias.
// SPLIT: write half2 to [B,H,L,DK]; z==0 additionally scaled by QSCALE.
// ---------------------------------------------------------------------------
#define ASTH 20                         // A row stride (words) = 32 halfs + pad
#define BSTH 20
#define ASWH (128 * ASTH)               // 2560 words
#define STGWH (ASWH + 256 * BSTH)       // 7680 words = 30720 B / stage
#define NSTG 4
#define GEMM_SMEM (NSTG * STGWH * 4)    // 122880 B

template <bool SPLIT>
__global__ __launch_bounds__(256, 1) void gemm_h(
    const __half* __restrict__ A0, const __half* __restrict__ A1,
    const __half* __restrict__ A2, const __half* __restrict__ Wt,
    const float* __restrict__ bias0, const float* __restrict__ bias1,
    const float* __restrict__ bias2, void* __restrict__ C0,
    void* __restrict__ C1, void* __restrict__ C2) {
    extern __shared__ uint32_t sh[];
    const uint32_t sbase = smem_u32(sh);
    const int z = blockIdx.z;
    const __half* A = z == 0 ? A0 : z == 1 ? A1 : A2;
    const __half* W = Wt + (size_t)z * D_ * N_;
    const float* bias = z == 0 ? bias0 : z == 1 ? bias1 : bias2;
    void* Cv = z == 0 ? C0 : z == 1 ? C1 : C2;

    const int tid = threadIdx.x;
    const int lane = tid & 31;
    const int warp = tid >> 5;
    const int wm = (warp >> 2) * 64;
    const int wn = (warp & 3) * 64;
    const int row0 = blockIdx.y * 128;
    const int col0 = blockIdx.x * 256;
    const int lr = lane >> 2;
    const int lc = lane & 3;
    const int l7 = lane & 7;
    const int lt1 = (lane >> 3) & 1;
    const int lt2 = lane >> 4;

    float acc[4][8][4];
#pragma unroll
    for (int i = 0; i < 4; i++)
#pragma unroll
        for (int j = 0; j < 8; j++)
#pragma unroll
            for (int e = 0; e < 4; e++) acc[i][j][e] = 0.0f;

    auto cpAB = [&](int kt, int s) {
#pragma unroll
        for (int it = 0; it < 2; it++) {           // A: 512 16B chunks
            const int cid = it * 256 + tid;
            const int r = cid >> 2, c = cid & 3;
            CP_ASYNC16(sbase + (s * STGWH + r * ASTH + c * 4) * 4,
                       &A[(size_t)(row0 + r) * D_ + kt * 32 + c * 8]);
        }
#pragma unroll
        for (int it = 0; it < 4; it++) {           // B: 1024 16B chunks
            const int cid = it * 256 + tid;
            const int r = cid >> 2, c = cid & 3;
            CP_ASYNC16(sbase + (s * STGWH + ASWH + r * BSTH + c * 4) * 4,
                       &W[(size_t)(col0 + r) * D_ + kt * 32 + c * 8]);
        }
        CP_COMMIT();
    };

    cpAB(0, 0);
    cpAB(1, 1);
    cpAB(2, 2);

    for (int kt = 0; kt < 32; kt++) {
        const int s = kt & 3;
        CP_WAIT2();
        __syncthreads();
        if (kt < 29) cpAB(kt + 3, (kt + 3) & 3);
        else CP_COMMIT();

        const uint32_t abase = sbase + (s * STGWH) * 4;
        const uint32_t bbase = abase + ASWH * 4;
#pragma unroll
        for (int step = 0; step < 2; step++) {
            const int kw = step * 8;  // word base of this k16 step
            uint32_t af[4][4];
#pragma unroll
            for (int mt = 0; mt < 4; mt++) {
                const int row = wm + mt * 16 + lt1 * 8 + l7;
                LDSM_X4(af[mt][0], af[mt][1], af[mt][2], af[mt][3],
                        abase + (row * ASTH + kw + lt2 * 4) * 4);
            }
#pragma unroll
            for (int ntp = 0; ntp < 4; ntp++) {
                uint32_t bf0, bf1, bf2, bf3;
                const int nr = wn + (ntp * 2 + lt2) * 8 + l7;
                LDSM_X4(bf0, bf1, bf2, bf3,
                        bbase + (nr * BSTH + kw + lt1 * 4) * 4);
#pragma unroll
                for (int mt = 0; mt < 4; mt++) {
                    mma_f16(acc[mt][ntp * 2], af[mt], bf0, bf1);
                    mma_f16(acc[mt][ntp * 2 + 1], af[mt], bf2, bf3);
                }
            }
        }
    }

    // epilogue
    const float sc = (SPLIT && z == 0) ? QSCALE : 1.0f;
#pragma unroll
    for (int mt = 0; mt < 4; mt++) {
#pragma unroll
        for (int nt = 0; nt < 8; nt++) {
            const int c = col0 + wn + nt * 8 + 2 * lc;
            const float bz0 = bias[c], bz1 = bias[c + 1];
#pragma unroll
            for (int half = 0; half < 2; half++) {
                const int m = row0 + wm + mt * 16 + lr + half * 8;
                const float v0 = (acc[mt][nt][half * 2 + 0] + bz0) * sc;
                const float v1 = (acc[mt][nt][half * 2 + 1] + bz1) * sc;
                if (SPLIT) {
                    const int b = m >> 11, l = m & (L_ - 1);
                    const int h = c >> 6, dk = c & (DK_ - 1);
                    __half* C = (__half*)Cv;
                    *(uint32_t*)&C[((((size_t)b * H_ + h) * L_) + l) * DK_ +
                                   dk] = h2pack(v1, v0);
                } else {
                    float* C = (float*)Cv;
                    C[(size_t)m * N_ + c] = v0;
                    C[(size_t)m * N_ + c + 1] = v1;
                }
            }
        }
    }
}

// ---------------------------------------------------------------------------
// fp16 flash attention: BM=128, BN=64, 8 warps x 16 rows.
// Q pre-scaled fragments in regs; P stays in registers (fp16 frag layout);
// V consumed via ldmatrix.trans; K via ldmatrix.
// smem halfs: K[2][64x72] | V[2][64x72] | Q[128x72]  = 55296 B
// ---------------------------------------------------------------------------
#define KVSTR 36                         // words per row (72 halfs)
#define KOFF(s) ((s) * (64 * KVSTR))
#define VOFF(s) (2 * 64 * KVSTR + (s) * (64 * KVSTR))
#define QOFF (4 * 64 * KVSTR)            // 9216 words
#define ATTN_SMEM ((QOFF + 128 * KVSTR) * 4)  // 55296 B

__global__ __launch_bounds__(256, 2) void attn_h(
    const __half* __restrict__ q, const __half* __restrict__ k,
    const __half* __restrict__ v, __half* __restrict__ ctx) {
    extern __shared__ uint32_t sh[];
    const uint32_t sbase = smem_u32(sh);
    const int tid = threadIdx.x;
    const int lane = tid & 31;
    const int warp = tid >> 5;
    const int lr = lane >> 2;
    const int lc = lane & 3;
    const int m0 = warp * 16;
    const int bh = blockIdx.y;
    const int q0 = blockIdx.x * 128;
    const int l7 = lane & 7;
    const int lt1 = (lane >> 3) & 1;
    const int lt2 = lane >> 4;

    const __half* qbase = q + (size_t)bh * L_ * DK_ + (size_t)q0 * DK_;
    const __half* kbase = k + (size_t)bh * L_ * DK_;
    const __half* vbase = v + (size_t)bh * L_ * DK_;

    // each 16B chunk covers 8 halfs = 4 smem WORDS (c*4, not c*2!)
    auto cpKV = [&](int jn, int s) {
#pragma unroll
        for (int it = 0; it < 2; it++) {   // K: 512 chunks
            const int cid = it * 256 + tid;
            const int r = cid >> 3, c = cid & 7;
            CP_ASYNC16(sbase + (KOFF(s) + r * KVSTR + c * 4) * 4,
                       &kbase[(size_t)(jn * 64 + r) * DK_ + c * 8]);
        }
#pragma unroll
        for (int it = 0; it < 2; it++) {   // V: 512 chunks
            const int cid = it * 256 + tid;
            const int r = cid >> 3, c = cid & 7;
            CP_ASYNC16(sbase + (VOFF(s) + r * KVSTR + c * 4) * 4,
                       &vbase[(size_t)(jn * 64 + r) * DK_ + c * 8]);
        }
        CP_COMMIT();
    };

    // stage Q (1024 chunks) + first KV tile
#pragma unroll
    for (int it = 0; it < 4; it++) {
        const int cid = it * 256 + tid;
        const int r = cid >> 3, c = cid & 7;
        CP_ASYNC16(sbase + (QOFF + r * KVSTR + c * 4) * 4,
                   &qbase[(size_t)r * DK_ + c * 8]);
    }
    CP_COMMIT();
    cpKV(0, 0);
    CP_WAIT0();
    __syncthreads();

    // Q fragments (already scaled by QSCALE in projection epilogue)
    uint32_t qf[4][4];
#pragma unroll
    for (int g = 0; g < 4; g++) {
        const int row = m0 + lt1 * 8 + l7;
        LDSM_X4(qf[g][0], qf[g][1], qf[g][2], qf[g][3],
                sbase + (QOFF + row * KVSTR + g * 8 + lt2 * 4) * 4);
    }

    float oacc[8][4];
#pragma unroll
    for (int vt = 0; vt < 8; vt++)
#pragma unroll
        for (int e = 0; e < 4; e++) oacc[vt][e] = 0.0f;
    float mrow0 = -1e30f, mrow1 = -1e30f, lrow0 = 0.0f, lrow1 = 0.0f;

    for (int jt = 0; jt < 32; jt++) {
        const int s = jt & 1;
        if (jt > 0) {
            CP_WAIT0();
            __syncthreads();
        }
        if (jt < 31) cpKV(jt + 1, s ^ 1);

        // S = Q K^T (base-2 logits)
        float sacc[8][4];
#pragma unroll
        for (int nt = 0; nt < 8; nt++)
#pragma unroll
            for (int e = 0; e < 4; e++) sacc[nt][e] = 0.0f;
#pragma unroll
        for (int g = 0; g < 4; g++) {
#pragma unroll
            for (int ntp = 0; ntp < 4; ntp++) {
                uint32_t bf0, bf1, bf2, bf3;
                const int nr = (ntp * 2 + lt2) * 8 + l7;
                LDSM_X4(bf0, bf1, bf2, bf3,
                        sbase + (KOFF(s) + nr * KVSTR + g * 8 + lt1 * 4) * 4);
                mma_f16(sacc[ntp * 2], qf[g], bf0, bf1);
                mma_f16(sacc[ntp * 2 + 1], qf[g], bf2, bf3);
            }
        }

        // online softmax (ex2 domain); pack P into fp16 A-fragments
        float mx0 = -1e30f, mx1 = -1e30f;
#pragma unroll
        for (int nt = 0; nt < 8; nt++) {
            mx0 = fmaxf(mx0, fmaxf(sacc[nt][0], sacc[nt][1]));
            mx1 = fmaxf(mx1, fmaxf(sacc[nt][2], sacc[nt][3]));
        }
        mx0 = fmaxf(mx0, __shfl_xor_sync(0xffffffffu, mx0, 1));
        mx0 = fmaxf(mx0, __shfl_xor_sync(0xffffffffu, mx0, 2));
        mx1 = fmaxf(mx1, __shfl_xor_sync(0xffffffffu, mx1, 1));
        mx1 = fmaxf(mx1, __shfl_xor_sync(0xffffffffu, mx1, 2));
        const float mn0 = fmaxf(mrow0, mx0);
        const float mn1 = fmaxf(mrow1, mx1);
        const float al0 = ex2(mrow0 - mn0);
        const float al1 = ex2(mrow1 - mn1);
        mrow0 = mn0; mrow1 = mn1;

        uint32_t pf[4][4];
        float sum0 = 0.0f, sum1 = 0.0f;
#pragma unroll
        for (int nt = 0; nt < 8; nt++) {
            const float p0 = ex2(sacc[nt][0] - mn0);
            const float p1 = ex2(sacc[nt][1] - mn0);
            const float p2 = ex2(sacc[nt][2] - mn1);
            const float p3 = ex2(sacc[nt][3] - mn1);
            sum0 += p0 + p1; sum1 += p2 + p3;
            const int g = nt >> 1;
            const int o = (nt & 1) * 2;
            pf[g][o + 0] = h2pack(p1, p0);   // rows lr,   k pair
            pf[g][o + 1] = h2pack(p3, p2);   // rows lr+8, k pair
        }
        sum0 += __shfl_xor_sync(0xffffffffu, sum0, 1);
        sum0 += __shfl_xor_sync(0xffffffffu, sum0, 2);
        sum1 += __shfl_xor_sync(0xffffffffu, sum1, 1);
        sum1 += __shfl_xor_sync(0xffffffffu, sum1, 2);
        lrow0 = lrow0 * al0 + sum0;
        lrow1 = lrow1 * al1 + sum1;
#pragma unroll
        for (int vt = 0; vt < 8; vt++) {
            oacc[vt][0] *= al0; oacc[vt][1] *= al0;
            oacc[vt][2] *= al1; oacc[vt][3] *= al1;
        }

        // O += P V   (V fragments via ldmatrix.trans from [p][n] storage)
#pragma unroll
        for (int g = 0; g < 4; g++) {
#pragma unroll
            for (int vtp = 0; vtp < 4; vtp++) {
                uint32_t bf0, bf1, bf2, bf3;
                const int vr = 16 * g + lt1 * 8 + l7;
                LDSM_X4T(bf0, bf1, bf2, bf3,
                         sbase + (VOFF(s) + vr * KVSTR + (vtp * 2 + lt2) * 4) * 4);
                mma_f16(oacc[vtp * 2], pf[g], bf0, bf1);
                mma_f16(oacc[vtp * 2 + 1], pf[g], bf2, bf3);
            }
        }
    }

    // epilogue: normalize, write half2 ctx [B, L, H*DV]
    const int b = bh >> 4;
    const int h = bh & (H_ - 1);
    const float inv0 = 1.0f / lrow0;
    const float inv1 = 1.0f / lrow1;
    const int r0 = q0 + m0 + lr;
#pragma unroll
    for (int vt = 0; vt < 8; vt++) {
        const int c = h * DK_ + vt * 8 + 2 * lc;
        *(uint32_t*)&ctx[((size_t)b * L_ + r0) * N_ + c] =
            h2pack(oacc[vt][1] * inv0, oacc[vt][0] * inv0);
        *(uint32_t*)&ctx[((size_t)b * L_ + r0 + 8) * N_ + c] =
            h2pack(oacc[vt][3] * inv1, oacc[vt][2] * inv1);
    }
}

// ---------------------------------------------------------------------------
extern "C" void kernel_launch(void* const* d_in, const int* in_sizes, int n_in,
                              void* d_out, int out_size) {
    const float* query = (const float*)d_in[0];
    const float* key   = (const float*)d_in[1];
    const float* value = (const float*)d_in[2];
    const float* W_q   = (const float*)d_in[3];
    const float* b_q   = (const float*)d_in[4];
    const float* W_k   = (const float*)d_in[5];
    const float* b_k   = (const float*)d_in[6];
    const float* W_v   = (const float*)d_in[7];
    const float* b_v   = (const float*)d_in[8];
    const float* W_o   = (const float*)d_in[9];
    const float* b_o   = (const float*)d_in[10];
    float* out = (float*)d_out;

    __half *qp, *kp, *vp, *cp, *wt, *qin, *kin, *vin;
    cudaGetSymbolAddress((void**)&qp, g_q);
    cudaGetSymbolAddress((void**)&kp, g_k);
    cudaGetSymbolAddress((void**)&vp, g_v);
    cudaGetSymbolAddress((void**)&cp, g_ctx);
    cudaGetSymbolAddress((void**)&wt, g_wth);
    cudaGetSymbolAddress((void**)&qin, g_qin);
    cudaGetSymbolAddress((void**)&kin, g_kin);
    cudaGetSymbolAddress((void**)&vin, g_vin);

    cudaFuncSetAttribute(gemm_h<true>,
                         cudaFuncAttributeMaxDynamicSharedMemorySize, GEMM_SMEM);
    cudaFuncSetAttribute(gemm_h<false>,
                         cudaFuncAttributeMaxDynamicSharedMemorySize, GEMM_SMEM);
    cudaFuncSetAttribute(attn_h, cudaFuncAttributeMaxDynamicSharedMemorySize,
                         ATTN_SMEM);

    // prepass: inputs -> fp16; weights -> fp16 transposed [n][k]
    cvt_in<<<12288, 256>>>(query, key, value, qin, kin, vin);
    transp_w<<<dim3(32, 32, 4), dim3(32, 8)>>>(W_q, W_k, W_v, W_o, wt);

    // fused QKV projections (z selects input/bias/output; z==0 scaled)
    dim3 ggrid(N_ / 256, M_ / 128, 3);  // (4, 64, 3)
    gemm_h<true><<<ggrid, 256, GEMM_SMEM>>>(qin, kin, vin, wt, b_q, b_k, b_v,
                                            qp, kp, vp);

    dim3 agrid(L_ / 128, B_ * H_);      // (16, 64)
    attn_h<<<agrid, 256, ATTN_SMEM>>>(qp, kp, vp, cp);

    // output projection: ctx (half) @ W_o + b_o -> f32 out
    dim3 ogrid(N_ / 256, M_ / 128, 1);
    gemm_h<false><<<ogrid, 256, GEMM_SMEM>>>(cp, cp, cp, wt + 3ull * D_ * N_,
                                             b_o, b_o, b_o, out, out, out);
}

// round 16
// speedup vs baseline: 2.0087x; 1.1039x over previous
#include <cuda_runtime.h>
#include <cuda_fp16.h>
#include <math.h>
#include <stdint.h>

// Problem constants
#define B_  4
#define L_  2048
#define D_  1024
#define H_  16
#define DK_ 64
#define M_  (B_ * L_)      // 8192
#define N_  (H_ * DK_)     // 1024

#define QSCALE 0.18033688011112042f  // 0.125 * log2(e)

// Scratch (device globals — no runtime allocation allowed). 16B+ alignment
// required for cp.async/uint4 access paths.
__device__ __align__(256) __half g_q[(size_t)B_ * H_ * L_ * DK_];
__device__ __align__(256) __half g_k[(size_t)B_ * H_ * L_ * DK_];
__device__ __align__(256) __half g_v[(size_t)B_ * H_ * L_ * DK_];
__device__ __align__(256) __half g_ctx[(size_t)M_ * N_];
__device__ __align__(256) __half g_wth[4ull * D_ * N_];   // W^T: [n][k]
__device__ __align__(256) __half g_qin[(size_t)M_ * D_];
__device__ __align__(256) __half g_kin[(size_t)M_ * D_];
__device__ __align__(256) __half g_vin[(size_t)M_ * D_];

// ---------------------------------------------------------------------------
// helpers
// ---------------------------------------------------------------------------
__device__ __forceinline__ uint32_t smem_u32(const void* p) {
    uint32_t a;
    asm("{ .reg .u64 t; cvta.to.shared.u64 t, %1; cvt.u32.u64 %0, t; }"
        : "=r"(a) : "l"(p));
    return a;
}
__device__ __forceinline__ float ex2(float x) {
    float r;
    asm("ex2.approx.ftz.f32 %0, %1;" : "=f"(r) : "f"(x));
    return r;
}
// pack {hi, lo} floats -> one f16x2 register (lo = lower half)
__device__ __forceinline__ uint32_t h2pack(float hi, float lo) {
    uint32_t d;
    asm("cvt.rn.f16x2.f32 %0, %1, %2;" : "=r"(d) : "f"(hi), "f"(lo));
    return d;
}
__device__ __forceinline__ void mma_f16(float* c, const uint32_t* a,
                                        uint32_t b0, uint32_t b1) {
    asm volatile(
        "mma.sync.aligned.m16n8k16.row.col.f32.f16.f16.f32 "
        "{%0,%1,%2,%3},{%4,%5,%6,%7},{%8,%9},{%0,%1,%2,%3};"
        : "+f"(c[0]), "+f"(c[1]), "+f"(c[2]), "+f"(c[3])
        : "r"(a[0]), "r"(a[1]), "r"(a[2]), "r"(a[3]), "r"(b0), "r"(b1));
}
#define LDSM_X4(r0, r1, r2, r3, addr)                                   \
    asm volatile(                                                       \
        "ldmatrix.sync.aligned.m8n8.x4.shared.b16 {%0,%1,%2,%3}, [%4];" \
        : "=r"(r0), "=r"(r1), "=r"(r2), "=r"(r3) : "r"(addr))
#define LDSM_X4T(r0, r1, r2, r3, addr)                                        \
    asm volatile(                                                             \
        "ldmatrix.sync.aligned.m8n8.x4.trans.shared.b16 {%0,%1,%2,%3}, [%4];" \
        : "=r"(r0), "=r"(r1), "=r"(r2), "=r"(r3) : "r"(addr))
#define CP_ASYNC16(dst, src)                                     \
    asm volatile("cp.async.cg.shared.global [%0], [%1], 16;" :: \
                     "r"(dst), "l"(src))
#define CP_COMMIT() asm volatile("cp.async.commit_group;")
#define CP_WAIT0() asm volatile("cp.async.wait_group 0;")
#define CP_WAIT2() asm volatile("cp.async.wait_group 2;")

// ---------------------------------------------------------------------------
// Prepass 1: inputs fp32 -> fp16. 3 segments x 4096 blocks x 2048 elems.
// ---------------------------------------------------------------------------
__global__ __launch_bounds__(256) void cvt_in(
    const float* __restrict__ q, const float* __restrict__ k,
    const float* __restrict__ v, __half* __restrict__ qo,
    __half* __restrict__ ko, __half* __restrict__ vo) {
    const int blk = blockIdx.x;
    const int seg = blk >> 12;
    const int base = blk & 4095;
    const float* src = seg == 0 ? q : seg == 1 ? k : v;
    __half* dst = seg == 0 ? qo : seg == 1 ? ko : vo;
    const size_t i = (size_t)base * 2048 + threadIdx.x * 8;
    float4 a = *(const float4*)&src[i];
    float4 b = *(const float4*)&src[i + 4];
    uint4 o;
    o.x = h2pack(a.y, a.x); o.y = h2pack(a.w, a.z);
    o.z = h2pack(b.y, b.x); o.w = h2pack(b.w, b.z);
    *(uint4*)&dst[i] = o;
}

// ---------------------------------------------------------------------------
// Prepass 2: weights fp32 [k][n] -> fp16 transposed [n][k] (4 weights via z)
// ---------------------------------------------------------------------------
__global__ __launch_bounds__(256) void transp_w(
    const float* __restrict__ Wq, const float* __restrict__ Wk,
    const float* __restrict__ Wv, const float* __restrict__ Wo,
    __half* __restrict__ wt) {
    __shared__ float t[32][33];
    const int z = blockIdx.z;
    const float* W = z == 0 ? Wq : z == 1 ? Wk : z == 2 ? Wv : Wo;
    __half* Wt = wt + (size_t)z * D_ * N_;
    const int bx = blockIdx.x * 32, by = blockIdx.y * 32;
    const int x = threadIdx.x, y = threadIdx.y;  // 32 x 8
#pragma unroll
    for (int i = 0; i < 32; i += 8)
        t[y + i][x] = W[(size_t)(by + y + i) * N_ + bx + x];
    __syncthreads();
#pragma unroll
    for (int i = 0; i < 32; i += 8)
        Wt[(size_t)(bx + y + i) * D_ + by + x] = __float2half_rn(t[x][y + i]);
}

// ---------------------------------------------------------------------------
// fp16 GEMM: block 128x128, warp tile 64x32 (8 warps as 2x4), BK=32 halfs,
// 4-stage cp.async, ldmatrix fragments, 2 CTAs/SM. QKV fused via gridDim.z.
// SPLIT: write half2 to [B,H,L,DK]; z==0 additionally scaled by QSCALE.
// ---------------------------------------------------------------------------
#define ASTH 20                         // A row stride (words) = 32 halfs + pad
#define BSTH 20
#define ASWH (128 * ASTH)               // 2560 words
#define STGWH (ASWH + 128 * BSTH)       // 5120 words = 20480 B / stage
#define NSTG 4
#define GEMM_SMEM (NSTG * STGWH * 4)    // 81920 B

template <bool SPLIT>
__global__ __launch_bounds__(256, 2) void gemm_h(
    const __half* __restrict__ A0, const __half* __restrict__ A1,
    const __half* __restrict__ A2, const __half* __restrict__ Wt,
    const float* __restrict__ bias0, const float* __restrict__ bias1,
    const float* __restrict__ bias2, void* __restrict__ C0,
    void* __restrict__ C1, void* __restrict__ C2) {
    extern __shared__ uint32_t sh[];
    const uint32_t sbase = smem_u32(sh);
    const int z = blockIdx.z;
    const __half* A = z == 0 ? A0 : z == 1 ? A1 : A2;
    const __half* W = Wt + (size_t)z * D_ * N_;
    const float* bias = z == 0 ? bias0 : z == 1 ? bias1 : bias2;
    void* Cv = z == 0 ? C0 : z == 1 ? C1 : C2;

    const int tid = threadIdx.x;
    const int lane = tid & 31;
    const int warp = tid >> 5;
    const int wm = (warp >> 2) * 64;    // 2 row groups
    const int wn = (warp & 3) * 32;     // 4 col groups
    const int row0 = blockIdx.y * 128;
    const int col0 = blockIdx.x * 128;
    const int lr = lane >> 2;
    const int lc = lane & 3;
    const int l7 = lane & 7;
    const int lt1 = (lane >> 3) & 1;
    const int lt2 = lane >> 4;

    float acc[4][4][4];
#pragma unroll
    for (int i = 0; i < 4; i++)
#pragma unroll
        for (int j = 0; j < 4; j++)
#pragma unroll
            for (int e = 0; e < 4; e++) acc[i][j][e] = 0.0f;

    auto cpAB = [&](int kt, int s) {
#pragma unroll
        for (int it = 0; it < 2; it++) {           // A: 512 16B chunks
            const int cid = it * 256 + tid;
            const int r = cid >> 2, c = cid & 3;
            CP_ASYNC16(sbase + (s * STGWH + r * ASTH + c * 4) * 4,
                       &A[(size_t)(row0 + r) * D_ + kt * 32 + c * 8]);
        }
#pragma unroll
        for (int it = 0; it < 2; it++) {           // B: 512 16B chunks
            const int cid = it * 256 + tid;
            const int r = cid >> 2, c = cid & 3;
            CP_ASYNC16(sbase + (s * STGWH + ASWH + r * BSTH + c * 4) * 4,
                       &W[(size_t)(col0 + r) * D_ + kt * 32 + c * 8]);
        }
        CP_COMMIT();
    };

    cpAB(0, 0);
    cpAB(1, 1);
    cpAB(2, 2);

    for (int kt = 0; kt < 32; kt++) {
        const int s = kt & 3;
        CP_WAIT2();
        __syncthreads();
        if (kt < 29) cpAB(kt + 3, (kt + 3) & 3);
        else CP_COMMIT();

        const uint32_t abase = sbase + (s * STGWH) * 4;
        const uint32_t bbase = abase + ASWH * 4;
#pragma unroll
        for (int step = 0; step < 2; step++) {
            const int kw = step * 8;  // word base of this k16 step
            uint32_t af[4][4];
#pragma unroll
            for (int mt = 0; mt < 4; mt++) {
                const int row = wm + mt * 16 + lt1 * 8 + l7;
                LDSM_X4(af[mt][0], af[mt][1], af[mt][2], af[mt][3],
                        abase + (row * ASTH + kw + lt2 * 4) * 4);
            }
#pragma unroll
            for (int ntp = 0; ntp < 2; ntp++) {
                uint32_t bf0, bf1, bf2, bf3;
                const int nr = wn + (ntp * 2 + lt2) * 8 + l7;
                LDSM_X4(bf0, bf1, bf2, bf3,
                        bbase + (nr * BSTH + kw + lt1 * 4) * 4);
#pragma unroll
                for (int mt = 0; mt < 4; mt++) {
                    mma_f16(acc[mt][ntp * 2], af[mt], bf0, bf1);
                    mma_f16(acc[mt][ntp * 2 + 1], af[mt], bf2, bf3);
                }
            }
        }
    }

    // epilogue
    const float sc = (SPLIT && z == 0) ? QSCALE : 1.0f;
#pragma unroll
    for (int mt = 0; mt < 4; mt++) {
#pragma unroll
        for (int nt = 0; nt < 4; nt++) {
            const int c = col0 + wn + nt * 8 + 2 * lc;
            const float bz0 = bias[c], bz1 = bias[c + 1];
#pragma unroll
            for (int half = 0; half < 2; half++) {
                const int m = row0 + wm + mt * 16 + lr + half * 8;
                const float v0 = (acc[mt][nt][half * 2 + 0] + bz0) * sc;
                const float v1 = (acc[mt][nt][half * 2 + 1] + bz1) * sc;
                if (SPLIT) {
                    const int b = m >> 11, l = m & (L_ - 1);
                    const int h = c >> 6, dk = c & (DK_ - 1);
                    __half* C = (__half*)Cv;
                    *(uint32_t*)&C[((((size_t)b * H_ + h) * L_) + l) * DK_ +
                                   dk] = h2pack(v1, v0);
                } else {
                    float* C = (float*)Cv;
                    C[(size_t)m * N_ + c] = v0;
                    C[(size_t)m * N_ + c + 1] = v1;
                }
            }
        }
    }
}

// ---------------------------------------------------------------------------
// fp16 flash attention: BM=128, BN=64, 8 warps x 16 rows.
// Q pre-scaled fragments in regs; P stays in registers; V via ldmatrix.trans.
// l-sum is kept as per-thread partials; quad-reduced ONCE in the epilogue.
// smem halfs: K[2][64x72] | V[2][64x72] | Q[128x72]  = 55296 B
// ---------------------------------------------------------------------------
#define KVSTR 36                         // words per row (72 halfs)
#define KOFF(s) ((s) * (64 * KVSTR))
#define VOFF(s) (2 * 64 * KVSTR + (s) * (64 * KVSTR))
#define QOFF (4 * 64 * KVSTR)            // 9216 words
#define ATTN_SMEM ((QOFF + 128 * KVSTR) * 4)  // 55296 B

__global__ __launch_bounds__(256, 2) void attn_h(
    const __half* __restrict__ q, const __half* __restrict__ k,
    const __half* __restrict__ v, __half* __restrict__ ctx) {
    extern __shared__ uint32_t sh[];
    const uint32_t sbase = smem_u32(sh);
    const int tid = threadIdx.x;
    const int lane = tid & 31;
    const int warp = tid >> 5;
    const int lr = lane >> 2;
    const int lc = lane & 3;
    const int m0 = warp * 16;
    const int bh = blockIdx.y;
    const int q0 = blockIdx.x * 128;
    const int l7 = lane & 7;
    const int lt1 = (lane >> 3) & 1;
    const int lt2 = lane >> 4;

    const __half* qbase = q + (size_t)bh * L_ * DK_ + (size_t)q0 * DK_;
    const __half* kbase = k + (size_t)bh * L_ * DK_;
    const __half* vbase = v + (size_t)bh * L_ * DK_;

    // each 16B chunk covers 8 halfs = 4 smem WORDS
    auto cpKV = [&](int jn, int s) {
#pragma unroll
        for (int it = 0; it < 2; it++) {   // K: 512 chunks
            const int cid = it * 256 + tid;
            const int r = cid >> 3, c = cid & 7;
            CP_ASYNC16(sbase + (KOFF(s) + r * KVSTR + c * 4) * 4,
                       &kbase[(size_t)(jn * 64 + r) * DK_ + c * 8]);
        }
#pragma unroll
        for (int it = 0; it < 2; it++) {   // V: 512 chunks
            const int cid = it * 256 + tid;
            const int r = cid >> 3, c = cid & 7;
            CP_ASYNC16(sbase + (VOFF(s) + r * KVSTR + c * 4) * 4,
                       &vbase[(size_t)(jn * 64 + r) * DK_ + c * 8]);
        }
        CP_COMMIT();
    };

    // stage Q (1024 chunks) + first KV tile
#pragma unroll
    for (int it = 0; it < 4; it++) {
        const int cid = it * 256 + tid;
        const int r = cid >> 3, c = cid & 7;
        CP_ASYNC16(sbase + (QOFF + r * KVSTR + c * 4) * 4,
                   &qbase[(size_t)r * DK_ + c * 8]);
    }
    CP_COMMIT();
    cpKV(0, 0);
    CP_WAIT0();
    __syncthreads();

    // Q fragments (already scaled by QSCALE in projection epilogue)
    uint32_t qf[4][4];
#pragma unroll
    for (int g = 0; g < 4; g++) {
        const int row = m0 + lt1 * 8 + l7;
        LDSM_X4(qf[g][0], qf[g][1], qf[g][2], qf[g][3],
                sbase + (QOFF + row * KVSTR + g * 8 + lt2 * 4) * 4);
    }

    float oacc[8][4];
#pragma unroll
    for (int vt = 0; vt < 8; vt++)
#pragma unroll
        for (int e = 0; e < 4; e++) oacc[vt][e] = 0.0f;
    float mrow0 = -1e30f, mrow1 = -1e30f;
    float lrow0 = 0.0f, lrow1 = 0.0f;   // PER-THREAD partial sums (16 cols)

    for (int jt = 0; jt < 32; jt++) {
        const int s = jt & 1;
        if (jt > 0) {
            CP_WAIT0();
            __syncthreads();
        }
        if (jt < 31) cpKV(jt + 1, s ^ 1);

        // S = Q K^T (base-2 logits)
        float sacc[8][4];
#pragma unroll
        for (int nt = 0; nt < 8; nt++)
#pragma unroll
            for (int e = 0; e < 4; e++) sacc[nt][e] = 0.0f;
#pragma unroll
        for (int g = 0; g < 4; g++) {
#pragma unroll
            for (int ntp = 0; ntp < 4; ntp++) {
                uint32_t bf0, bf1, bf2, bf3;
                const int nr = (ntp * 2 + lt2) * 8 + l7;
                LDSM_X4(bf0, bf1, bf2, bf3,
                        sbase + (KOFF(s) + nr * KVSTR + g * 8 + lt1 * 4) * 4);
                mma_f16(sacc[ntp * 2], qf[g], bf0, bf1);
                mma_f16(sacc[ntp * 2 + 1], qf[g], bf2, bf3);
            }
        }

        // online softmax (ex2 domain); max still quad-reduced (needed for
        // stability); l-sum stays per-thread.
        float mx0 = -1e30f, mx1 = -1e30f;
#pragma unroll
        for (int nt = 0; nt < 8; nt++) {
            mx0 = fmaxf(mx0, fmaxf(sacc[nt][0], sacc[nt][1]));
            mx1 = fmaxf(mx1, fmaxf(sacc[nt][2], sacc[nt][3]));
        }
        mx0 = fmaxf(mx0, __shfl_xor_sync(0xffffffffu, mx0, 1));
        mx0 = fmaxf(mx0, __shfl_xor_sync(0xffffffffu, mx0, 2));
        mx1 = fmaxf(mx1, __shfl_xor_sync(0xffffffffu, mx1, 1));
        mx1 = fmaxf(mx1, __shfl_xor_sync(0xffffffffu, mx1, 2));
        const float mn0 = fmaxf(mrow0, mx0);
        const float mn1 = fmaxf(mrow1, mx1);
        const float al0 = ex2(mrow0 - mn0);
        const float al1 = ex2(mrow1 - mn1);
        mrow0 = mn0; mrow1 = mn1;

        uint32_t pf[4][4];
        float sum0 = 0.0f, sum1 = 0.0f;
#pragma unroll
        for (int nt = 0; nt < 8; nt++) {
            const float p0 = ex2(sacc[nt][0] - mn0);
            const float p1 = ex2(sacc[nt][1] - mn0);
            const float p2 = ex2(sacc[nt][2] - mn1);
            const float p3 = ex2(sacc[nt][3] - mn1);
            sum0 += p0 + p1; sum1 += p2 + p3;
            const int g = nt >> 1;
            const int o = (nt & 1) * 2;
            pf[g][o + 0] = h2pack(p1, p0);   // rows lr,   k pair
            pf[g][o + 1] = h2pack(p3, p2);   // rows lr+8, k pair
        }
        lrow0 = lrow0 * al0 + sum0;
        lrow1 = lrow1 * al1 + sum1;
#pragma unroll
        for (int vt = 0; vt < 8; vt++) {
            oacc[vt][0] *= al0; oacc[vt][1] *= al0;
            oacc[vt][2] *= al1; oacc[vt][3] *= al1;
        }

        // O += P V   (V fragments via ldmatrix.trans from [p][n] storage)
#pragma unroll
        for (int g = 0; g < 4; g++) {
#pragma unroll
            for (int vtp = 0; vtp < 4; vtp++) {
                uint32_t bf0, bf1, bf2, bf3;
                const int vr = 16 * g + lt1 * 8 + l7;
                LDSM_X4T(bf0, bf1, bf2, bf3,
                         sbase + (VOFF(s) + vr * KVSTR + (vtp * 2 + lt2) * 4) * 4);
                mma_f16(oacc[vtp * 2], pf[g], bf0, bf1);
                mma_f16(oacc[vtp * 2 + 1], pf[g], bf2, bf3);
            }
        }
    }

    // final l reduction across the quad (lanes lc 0..3 share the row)
    lrow0 += __shfl_xor_sync(0xffffffffu, lrow0, 1);
    lrow0 += __shfl_xor_sync(0xffffffffu, lrow0, 2);
    lrow1 += __shfl_xor_sync(0xffffffffu, lrow1, 1);
    lrow1 += __shfl_xor_sync(0xffffffffu, lrow1, 2);

    // epilogue: normalize, write half2 ctx [B, L, H*DV]
    const int b = bh >> 4;
    const int h = bh & (H_ - 1);
    const float inv0 = 1.0f / lrow0;
    const float inv1 = 1.0f / lrow1;
    const int r0 = q0 + m0 + lr;
#pragma unroll
    for (int vt = 0; vt < 8; vt++) {
        const int c = h * DK_ + vt * 8 + 2 * lc;
        *(uint32_t*)&ctx[((size_t)b * L_ + r0) * N_ + c] =
            h2pack(oacc[vt][1] * inv0, oacc[vt][0] * inv0);
        *(uint32_t*)&ctx[((size_t)b * L_ + r0 + 8) * N_ + c] =
            h2pack(oacc[vt][3] * inv1, oacc[vt][2] * inv1);
    }
}

// ---------------------------------------------------------------------------
extern "C" void kernel_launch(void* const* d_in, const int* in_sizes, int n_in,
                              void* d_out, int out_size) {
    const float* query = (const float*)d_in[0];
    const float* key   = (const float*)d_in[1];
    const float* value = (const float*)d_in[2];
    const float* W_q   = (const float*)d_in[3];
    const float* b_q   = (const float*)d_in[4];
    const float* W_k   = (const float*)d_in[5];
    const float* b_k   = (const float*)d_in[6];
    const float* W_v   = (const float*)d_in[7];
    const float* b_v   = (const float*)d_in[8];
    const float* W_o   = (const float*)d_in[9];
    const float* b_o   = (const float*)d_in[10];
    float* out = (float*)d_out;

    __half *qp, *kp, *vp, *cp, *wt, *qin, *kin, *vin;
    cudaGetSymbolAddress((void**)&qp, g_q);
    cudaGetSymbolAddress((void**)&kp, g_k);
    cudaGetSymbolAddress((void**)&vp, g_v);
    cudaGetSymbolAddress((void**)&cp, g_ctx);
    cudaGetSymbolAddress((void**)&wt, g_wth);
    cudaGetSymbolAddress((void**)&qin, g_qin);
    cudaGetSymbolAddress((void**)&kin, g_kin);
    cudaGetSymbolAddress((void**)&vin, g_vin);

    cudaFuncSetAttribute(gemm_h<true>,
                         cudaFuncAttributeMaxDynamicSharedMemorySize, GEMM_SMEM);
    cudaFuncSetAttribute(gemm_h<false>,
                         cudaFuncAttributeMaxDynamicSharedMemorySize, GEMM_SMEM);
    cudaFuncSetAttribute(attn_h, cudaFuncAttributeMaxDynamicSharedMemorySize,
                         ATTN_SMEM);

    // prepass: inputs -> fp16; weights -> fp16 transposed [n][k]
    cvt_in<<<12288, 256>>>(query, key, value, qin, kin, vin);
    transp_w<<<dim3(32, 32, 4), dim3(32, 8)>>>(W_q, W_k, W_v, W_o, wt);

    // fused QKV projections (z selects input/bias/output; z==0 scaled)
    dim3 ggrid(N_ / 128, M_ / 128, 3);  // (8, 64, 3)
    gemm_h<true><<<ggrid, 256, GEMM_SMEM>>>(qin, kin, vin, wt, b_q, b_k, b_v,
                                            qp, kp, vp);

    dim3 agrid(L_ / 128, B_ * H_);      // (16, 64)
    attn_h<<<agrid, 256, ATTN_SMEM>>>(qp, kp, vp, cp);

    // output projection: ctx (half) @ W_o + b_o -> f32 out
    dim3 ogrid(N_ / 128, M_ / 128, 1);
    gemm_h<false><<<ogrid, 256, GEMM_SMEM>>>(cp, cp, cp, wt + 3ull * D_ * N_,
                                             b_o, b_o, b_o, out, out, out);
}